// round 7
// baseline (speedup 1.0000x reference)
#include <cuda_runtime.h>
#include <cstddef>
#include <cstdint>

// Sizes: B=64, S=1024, E=256 (== proj dim), H=1024, G=4*H=4096
#define NB 64
#define NS 1024
#define NE 256
#define NH 1024
#define NG 4096

// ---------------- device scratch (static: no runtime allocation) ------------
__device__ float g_xg[2][(size_t)NS * NB * NG];  // 2 x 1 GiB  xg [dir][s][b][g]
__device__ float g_h[2][2][NB * NE];             // [parity][dir][b*256+p]
__device__ float g_a[2][NB * NH];                // [dir][b*1024+j]  o*tanh(c)
__device__ unsigned g_ctr[4];                    // [0]=all-grid, [1]=dir0, [2]=dir1

__device__ __forceinline__ float sigf(float x) { return 1.0f / (1.0f + __expf(-x)); }
__device__ __forceinline__ float tanh_f(float x) {
    float e = __expf(2.0f * x);
    return 1.0f - 2.0f / (e + 1.0f);
}

// 64x64 tile FMA core over one 32-wide K chunk. As/Bs are [64][33] (pad=1).
__device__ __forceinline__ void mm_tile(const float* __restrict__ As,
                                        const float* __restrict__ Bs,
                                        int tr, int tc, float acc[4][4]) {
#pragma unroll
    for (int kk = 0; kk < 32; kk++) {
        float av[4], bv[4];
#pragma unroll
        for (int r = 0; r < 4; r++) av[r] = As[(tr * 4 + r) * 33 + kk];
#pragma unroll
        for (int q = 0; q < 4; q++) bv[q] = Bs[(tc * 4 + q) * 33 + kk];
#pragma unroll
        for (int r = 0; r < 4; r++)
#pragma unroll
            for (int q = 0; q < 4; q++) acc[r][q] += av[r] * bv[q];
    }
}

// Device-scope barrier: monotonic counter, one arrival per block.
// Release: __threadfence before arrive. Acquire: post-spin reads use __ldcg
// (L2 = coherence point) and __syncthreads orders the block behind the spin.
__device__ __forceinline__ void gbar(unsigned* c, unsigned target) {
    __syncthreads();
    if (threadIdx.x == 0) {
        __threadfence();
        atomicAdd(c, 1u);
        while (atomicAdd(c, 0u) < target) { }
    }
    __syncthreads();
}

// --------------------------- init: zero state + counters --------------------
// grid 128 x 256 = 32768 threads
__global__ void init_kernel() {
    int i = blockIdx.x * blockDim.x + threadIdx.x;
    if (i < 4) g_ctr[i] = 0u;
    if (i < 2 * NB * NE) (&g_h[0][0][0])[i] = 0.0f;   // parity-0 h, both dirs
}

// --------------------------- the whole network ------------------------------
// grid 128 blocks x 256 threads, 1 block/SM, all co-resident.
// Block bid: dir = bid>>6, w = bid&63.
__global__ __launch_bounds__(256, 1) void lstm_kernel(
    const float* __restrict__ x,
    const float* __restrict__ Wihf, const float* __restrict__ Whhf,
    const float* __restrict__ bihf, const float* __restrict__ bhhf,
    const float* __restrict__ Whrf,
    const float* __restrict__ Wihb, const float* __restrict__ Whhb,
    const float* __restrict__ bihb, const float* __restrict__ bhhb,
    const float* __restrict__ Whrb,
    float* __restrict__ out)
{
    __shared__ float As[64 * 33];
    __shared__ float Bs[64 * 33];
    __shared__ float gs[64 * 65];

    const int bid = blockIdx.x;
    const int dir = bid >> 6;
    const int w   = bid & 63;
    const int tid = threadIdx.x;
    const int tr = tid >> 4, tc = tid & 15;

    // ---------------- phase 1: xg = x @ W_ih^T + (b_ih + b_hh) -------------
    // Block owns one 64-wide gate-column stripe for one direction; loops s.
    {
        const int n0 = w * 64;
        const float* __restrict__ W  = dir ? Wihb : Wihf;
        const float* __restrict__ bi = dir ? bihb : bihf;
        const float* __restrict__ bh = dir ? bhhb : bhhf;
        float* __restrict__ xo = g_xg[dir];

        float bias[4];
#pragma unroll
        for (int q = 0; q < 4; q++)
            bias[q] = bi[n0 + tc * 4 + q] + bh[n0 + tc * 4 + q];

        for (int s = 0; s < NS; s++) {
            float acc[4][4];
#pragma unroll
            for (int r = 0; r < 4; r++)
#pragma unroll
                for (int q = 0; q < 4; q++) acc[r][q] = 0.0f;

            for (int k0 = 0; k0 < NE; k0 += 32) {
#pragma unroll
                for (int i = 0; i < 2; i++) {
                    int f = tid + i * 256;
                    int r = f >> 3;
                    int kq = (f & 7) * 4;
                    float4 v = *(const float4*)&x[((size_t)r * NS + s) * NE + k0 + kq];
                    As[r * 33 + kq + 0] = v.x; As[r * 33 + kq + 1] = v.y;
                    As[r * 33 + kq + 2] = v.z; As[r * 33 + kq + 3] = v.w;
                    float4 ww = *(const float4*)&W[(size_t)(n0 + r) * NE + k0 + kq];
                    Bs[r * 33 + kq + 0] = ww.x; Bs[r * 33 + kq + 1] = ww.y;
                    Bs[r * 33 + kq + 2] = ww.z; Bs[r * 33 + kq + 3] = ww.w;
                }
                __syncthreads();
                mm_tile(As, Bs, tr, tc, acc);
                __syncthreads();
            }
#pragma unroll
            for (int r = 0; r < 4; r++) {
                int b = tr * 4 + r;
#pragma unroll
                for (int q = 0; q < 4; q++)
                    xo[((size_t)s * NB + b) * NG + n0 + tc * 4 + q] = acc[r][q] + bias[q];
            }
        }
    }
    gbar(&g_ctr[0], 128u);

    // ---------------- phase 2: the recurrence -------------------------------
    const float* __restrict__ Whh = dir ? Whhb : Whhf;
    const float* __restrict__ Whr = dir ? Whrb : Whrf;
    const float* __restrict__ xg  = g_xg[dir];
    unsigned* ctr = &g_ctr[1 + dir];

    const int j0 = w * 16;                 // gates: this block's 16 hidden units
    const int p0 = (w >> 4) * 64;          // proj: output column tile
    const int kbase = (w & 15) * 64;       // proj: K slice

    float creg[4] = {0.0f, 0.0f, 0.0f, 0.0f};   // cell state lives in registers

    for (int t = 0; t < NS; t++) {
        const int par = t & 1;
        const float* __restrict__ h = g_h[par][dir];
        float* __restrict__ hn = g_h[par ^ 1][dir];
        const int s_eff = dir ? (NS - 1 - t) : t;

        // zero my slice of the next-h accumulator (batch w, all 256 p)
        hn[w * 256 + tid] = 0.0f;

        // ---- gates GEMM: (64b x 64c) = h(64x256) @ Whh_cols(64x256)^T -----
        float acc[4][4];
#pragma unroll
        for (int r = 0; r < 4; r++)
#pragma unroll
            for (int q = 0; q < 4; q++) acc[r][q] = 0.0f;

        for (int k0 = 0; k0 < NE; k0 += 32) {
#pragma unroll
            for (int i = 0; i < 2; i++) {
                int f = tid + i * 256;
                int r = f >> 3;
                int kq = (f & 7) * 4;
                float4 v = __ldcg((const float4*)&h[r * NE + k0 + kq]);
                As[r * 33 + kq + 0] = v.x; As[r * 33 + kq + 1] = v.y;
                As[r * 33 + kq + 2] = v.z; As[r * 33 + kq + 3] = v.w;
                int g = ((r >> 4) << 10) + j0 + (r & 15);
                float4 ww = *(const float4*)&Whh[(size_t)g * NE + k0 + kq];
                Bs[r * 33 + kq + 0] = ww.x; Bs[r * 33 + kq + 1] = ww.y;
                Bs[r * 33 + kq + 2] = ww.z; Bs[r * 33 + kq + 3] = ww.w;
            }
            __syncthreads();
            mm_tile(As, Bs, tr, tc, acc);
            __syncthreads();
        }

        // combine with xg, stash gates as gs[c][b]
#pragma unroll
        for (int r = 0; r < 4; r++) {
            int b = tr * 4 + r;
#pragma unroll
            for (int q = 0; q < 4; q++) {
                int c = tc * 4 + q;
                int g = ((c >> 4) << 10) + j0 + (c & 15);
                gs[c * 65 + b] = acc[r][q] + __ldcg(&xg[((size_t)s_eff * NB + b) * NG + g]);
            }
        }
        __syncthreads();

        // ---- cell update (c in registers) ----------------------------------
#pragma unroll
        for (int i = 0; i < 4; i++) {
            int m = tid * 4 + i;           // 0..1023 = 16 units x 64 batches
            int jl = m & 15, b = m >> 4;
            float gi = gs[( 0 + jl) * 65 + b];
            float gf = gs[(16 + jl) * 65 + b];
            float gg = gs[(32 + jl) * 65 + b];
            float go = gs[(48 + jl) * 65 + b];
            float cn = sigf(gf) * creg[i] + sigf(gi) * tanh_f(gg);
            creg[i] = cn;
            g_a[dir][b * NH + j0 + jl] = sigf(go) * tanh_f(cn);
        }

        gbar(ctr, (unsigned)(2 * t + 1) * 64u);   // a complete

        // ---- projection: h_next += a(64x1024-slice) @ Whr_tile^T ----------
        float pacc[4][4];
#pragma unroll
        for (int r = 0; r < 4; r++)
#pragma unroll
            for (int q = 0; q < 4; q++) pacc[r][q] = 0.0f;

        for (int k0 = kbase; k0 < kbase + 64; k0 += 32) {
#pragma unroll
            for (int i = 0; i < 2; i++) {
                int f = tid + i * 256;
                int r = f >> 3;
                int kq = (f & 7) * 4;
                float4 v = __ldcg((const float4*)&g_a[dir][r * NH + k0 + kq]);
                As[r * 33 + kq + 0] = v.x; As[r * 33 + kq + 1] = v.y;
                As[r * 33 + kq + 2] = v.z; As[r * 33 + kq + 3] = v.w;
                float4 ww = *(const float4*)&Whr[(size_t)(p0 + r) * NH + k0 + kq];
                Bs[r * 33 + kq + 0] = ww.x; Bs[r * 33 + kq + 1] = ww.y;
                Bs[r * 33 + kq + 2] = ww.z; Bs[r * 33 + kq + 3] = ww.w;
            }
            __syncthreads();
            mm_tile(As, Bs, tr, tc, pacc);
            __syncthreads();
        }
#pragma unroll
        for (int r = 0; r < 4; r++) {
            int b = tr * 4 + r;
#pragma unroll
            for (int q = 0; q < 4; q++)
                atomicAdd(&hn[b * NE + p0 + tc * 4 + q], pacc[r][q]);
        }

        gbar(ctr, (unsigned)(2 * t + 2) * 64u);   // h_next complete

        // ---- stream this step's h to the output (batch w, coalesced) ------
        {
            float v = __ldcg(&hn[w * 256 + tid]);
            out[((size_t)w * NS + s_eff) * (2 * NE) + dir * NE + tid] = v;
        }
    }
}

// ----------------------------- launcher -------------------------------------
extern "C" void kernel_launch(void* const* d_in, const int* in_sizes, int n_in,
                              void* d_out, int out_size) {
    const float* x    = (const float*)d_in[0];
    const float* Wihf = (const float*)d_in[1];
    const float* Whhf = (const float*)d_in[2];
    const float* bihf = (const float*)d_in[3];
    const float* bhhf = (const float*)d_in[4];
    const float* Whrf = (const float*)d_in[5];
    const float* Wihb = (const float*)d_in[6];
    const float* Whhb = (const float*)d_in[7];
    const float* bihb = (const float*)d_in[8];
    const float* bhhb = (const float*)d_in[9];
    const float* Whrb = (const float*)d_in[10];
    float* out = (float*)d_out;

    init_kernel<<<128, 256>>>();
    lstm_kernel<<<128, 256>>>(x, Wihf, Whhf, bihf, bhhf, Whrf,
                              Wihb, Whhb, bihb, bhhb, Whrb, out);
}